// round 1
// baseline (speedup 1.0000x reference)
#include <cuda_runtime.h>
#include <math.h>

// Problem constants
#define BSZ 2
#define LSEQ 2048
#define EMB 1024
#define NH 16
#define DH 64
#define BH (BSZ*NH)          // 32
#define M1 (BSZ*LSEQ)        // 4096
#define N1 (3*EMB)           // 3072
#define KDIM EMB             // 1024

// Scratch (allocation-free): Q/K/V in [BH, L, D], ctx in [B, L, E]
__device__ float g_q[BH*LSEQ*DH];
__device__ float g_k[BH*LSEQ*DH];
__device__ float g_v[BH*LSEQ*DH];
__device__ float g_ctx[BSZ*LSEQ*EMB];

// ---------------------------------------------------------------------------
// C[M,N] = A[M,K] @ W[N,K]^T + bias[N]
// BM=128, BN=64, BK=16, 256 threads, 8x4 micro-tile.
// MODE 0: A = X, scatter output into g_q/g_k/g_v in [BH,L,D] layout
// MODE 1: A = g_ctx, write output row-major to Cout
// ---------------------------------------------------------------------------
template<int MODE>
__global__ __launch_bounds__(256)
void gemm_tn_kernel(const float* __restrict__ A_in,
                    const float* __restrict__ W,
                    const float* __restrict__ bias,
                    float* __restrict__ Cout,
                    int M, int N, int K)
{
    __shared__ float As[16][128];
    __shared__ float Bs[16][64];

    const float* A = (MODE == 0) ? A_in : g_ctx;

    const int tid = threadIdx.x;
    const int m0 = blockIdx.y * 128;
    const int n0 = blockIdx.x * 64;
    const int ty = tid >> 4;    // 0..15 -> 8 rows each
    const int tx = tid & 15;    // 0..15 -> 4 cols each

    float acc[8][4];
#pragma unroll
    for (int i = 0; i < 8; i++)
#pragma unroll
        for (int j = 0; j < 4; j++) acc[i][j] = 0.f;

    for (int k0 = 0; k0 < K; k0 += 16) {
        // A tile: 128 x 16 = 512 float4, 2 per thread
#pragma unroll
        for (int i = 0; i < 2; i++) {
            int idx = tid + i * 256;       // 0..511
            int r = idx >> 2;              // 0..127
            int q = idx & 3;               // 0..3
            float4 v = *(const float4*)(A + (size_t)(m0 + r) * K + k0 + q * 4);
            As[q*4+0][r] = v.x; As[q*4+1][r] = v.y;
            As[q*4+2][r] = v.z; As[q*4+3][r] = v.w;
        }
        // W tile: 64 x 16 = 256 float4, 1 per thread
        {
            int r = tid >> 2;              // 0..63
            int q = tid & 3;
            float4 v = *(const float4*)(W + (size_t)(n0 + r) * K + k0 + q * 4);
            Bs[q*4+0][r] = v.x; Bs[q*4+1][r] = v.y;
            Bs[q*4+2][r] = v.z; Bs[q*4+3][r] = v.w;
        }
        __syncthreads();

#pragma unroll
        for (int kk = 0; kk < 16; kk++) {
            float4 a0 = *(const float4*)&As[kk][ty * 8];
            float4 a1 = *(const float4*)&As[kk][ty * 8 + 4];
            float4 b0 = *(const float4*)&Bs[kk][tx * 4];
            float av[8] = {a0.x, a0.y, a0.z, a0.w, a1.x, a1.y, a1.z, a1.w};
            float bv[4] = {b0.x, b0.y, b0.z, b0.w};
#pragma unroll
            for (int i = 0; i < 8; i++)
#pragma unroll
                for (int j = 0; j < 4; j++)
                    acc[i][j] += av[i] * bv[j];
        }
        __syncthreads();
    }

#pragma unroll
    for (int i = 0; i < 8; i++) {
        int m = m0 + ty * 8 + i;
        int b = m >> 11;          // m / 2048
        int l = m & 2047;
#pragma unroll
        for (int j = 0; j < 4; j++) {
            int n = n0 + tx * 4 + j;
            float c = acc[i][j] + bias[n];
            if (MODE == 0) {
                int which = n >> 10;        // 0=q, 1=k, 2=v
                int e = n & 1023;
                int h = e >> 6;
                int d = e & 63;
                size_t dst = (((size_t)(b * NH + h)) * LSEQ + l) * DH + d;
                if (which == 0)      g_q[dst] = c;
                else if (which == 1) g_k[dst] = c;
                else                 g_v[dst] = c;
            } else {
                Cout[(size_t)m * N + n] = c;
            }
        }
    }
}

// ---------------------------------------------------------------------------
// Flash-style attention with additive bias.
// Grid: (L/128, B*H). Block: 256 threads.
// Each thread owns 2 q-rows (r, r+64) x 16 score cols / 16 output dims.
// Br = 128 query rows per block, Bc = 64 keys per inner tile.
// smem stride 72 floats (288B, 16B-aligned rows for float4).
// ---------------------------------------------------------------------------
#define SSTRIDE 72
#define ATTN_SMEM ((128 + 64 + 64 + 128) * SSTRIDE * 4)   // 110,592 B

__global__ __launch_bounds__(256)
void attn_kernel(const float* __restrict__ keb)
{
    extern __shared__ float sm[];
    float* Qs = sm;                        // 128 x SSTRIDE (pre-scaled)
    float* Ks = Qs + 128 * SSTRIDE;        // 64  x SSTRIDE
    float* Vs = Ks + 64 * SSTRIDE;         // 64  x SSTRIDE
    float* Ps = Vs + 64 * SSTRIDE;         // 128 x SSTRIDE

    const int tid = threadIdx.x;
    const int bh = blockIdx.y;             // 0..31
    const int q0 = blockIdx.x * 128;
    const int r  = tid >> 2;               // 0..63 (rows r and r+64)
    const int tx = tid & 3;                // 0..3
    const int d0 = tx * 16;

    const float scale = 0.125f;            // 1/sqrt(64)
    const float* Qg = g_q + (size_t)bh * LSEQ * DH;
    const float* Kg = g_k + (size_t)bh * LSEQ * DH;
    const float* Vg = g_v + (size_t)bh * LSEQ * DH;
    const float* Bg = keb + (size_t)bh * LSEQ * LSEQ;

    // Load Q tile (pre-scaled): 128x64 floats = 2048 float4, 8 per thread
#pragma unroll
    for (int i = 0; i < 8; i++) {
        int idx = tid + i * 256;           // 0..2047
        int rr = idx >> 4;                 // 0..127
        int c4 = idx & 15;                 // 0..15
        float4 v = *(const float4*)(Qg + (size_t)(q0 + rr) * DH + c4 * 4);
        Qs[rr * SSTRIDE + c4*4 + 0] = v.x * scale;
        Qs[rr * SSTRIDE + c4*4 + 1] = v.y * scale;
        Qs[rr * SSTRIDE + c4*4 + 2] = v.z * scale;
        Qs[rr * SSTRIDE + c4*4 + 3] = v.w * scale;
    }

    float m0v = -INFINITY, m1v = -INFINITY;
    float l0 = 0.f, l1 = 0.f;
    float o0[16], o1[16];
#pragma unroll
    for (int j = 0; j < 16; j++) { o0[j] = 0.f; o1[j] = 0.f; }

    for (int k0 = 0; k0 < LSEQ; k0 += 64) {
        __syncthreads();   // previous PV reads done before overwrite
        // Load K,V tiles: 64x64 each = 1024 float4 each, 4 per thread
#pragma unroll
        for (int i = 0; i < 4; i++) {
            int idx = tid + i * 256;
            int rr = idx >> 4;
            int c4 = idx & 15;
            float4 kv = *(const float4*)(Kg + (size_t)(k0 + rr) * DH + c4 * 4);
            Ks[rr * SSTRIDE + c4*4 + 0] = kv.x;
            Ks[rr * SSTRIDE + c4*4 + 1] = kv.y;
            Ks[rr * SSTRIDE + c4*4 + 2] = kv.z;
            Ks[rr * SSTRIDE + c4*4 + 3] = kv.w;
            float4 vv = *(const float4*)(Vg + (size_t)(k0 + rr) * DH + c4 * 4);
            Vs[rr * SSTRIDE + c4*4 + 0] = vv.x;
            Vs[rr * SSTRIDE + c4*4 + 1] = vv.y;
            Vs[rr * SSTRIDE + c4*4 + 2] = vv.z;
            Vs[rr * SSTRIDE + c4*4 + 3] = vv.w;
        }
        __syncthreads();

        // scores init = bias, then += (q*scale) . k
        float s0[16], s1[16];
#pragma unroll
        for (int v4 = 0; v4 < 4; v4++) {
            float4 b0 = *(const float4*)(Bg + (size_t)(q0 + r) * LSEQ + k0 + d0 + v4 * 4);
            float4 b1 = *(const float4*)(Bg + (size_t)(q0 + r + 64) * LSEQ + k0 + d0 + v4 * 4);
            s0[v4*4+0] = b0.x; s0[v4*4+1] = b0.y; s0[v4*4+2] = b0.z; s0[v4*4+3] = b0.w;
            s1[v4*4+0] = b1.x; s1[v4*4+1] = b1.y; s1[v4*4+2] = b1.z; s1[v4*4+3] = b1.w;
        }

#pragma unroll 4
        for (int d4 = 0; d4 < 16; d4++) {
            float4 qa = *(const float4*)&Qs[r * SSTRIDE + d4 * 4];
            float4 qb = *(const float4*)&Qs[(r + 64) * SSTRIDE + d4 * 4];
#pragma unroll
            for (int j = 0; j < 16; j++) {
                float4 kv = *(const float4*)&Ks[(d0 + j) * SSTRIDE + d4 * 4];
                s0[j] += qa.x * kv.x + qa.y * kv.y + qa.z * kv.z + qa.w * kv.w;
                s1[j] += qb.x * kv.x + qb.y * kv.y + qb.z * kv.z + qb.w * kv.w;
            }
        }

        // row max (4 threads per row, contiguous lanes -> xor shfl)
        float mx0 = -INFINITY, mx1 = -INFINITY;
#pragma unroll
        for (int j = 0; j < 16; j++) { mx0 = fmaxf(mx0, s0[j]); mx1 = fmaxf(mx1, s1[j]); }
        mx0 = fmaxf(mx0, __shfl_xor_sync(0xffffffffu, mx0, 1));
        mx0 = fmaxf(mx0, __shfl_xor_sync(0xffffffffu, mx0, 2));
        mx1 = fmaxf(mx1, __shfl_xor_sync(0xffffffffu, mx1, 1));
        mx1 = fmaxf(mx1, __shfl_xor_sync(0xffffffffu, mx1, 2));

        float mn0 = fmaxf(m0v, mx0);
        float mn1 = fmaxf(m1v, mx1);
        float c0 = __expf(m0v - mn0);
        float c1 = __expf(m1v - mn1);
        m0v = mn0; m1v = mn1;

        float ls0 = 0.f, ls1 = 0.f;
#pragma unroll
        for (int j = 0; j < 16; j++) {
            float p0 = __expf(s0[j] - mn0);
            float p1 = __expf(s1[j] - mn1);
            s0[j] = p0; s1[j] = p1;
            ls0 += p0; ls1 += p1;
        }
        ls0 += __shfl_xor_sync(0xffffffffu, ls0, 1);
        ls0 += __shfl_xor_sync(0xffffffffu, ls0, 2);
        ls1 += __shfl_xor_sync(0xffffffffu, ls1, 1);
        ls1 += __shfl_xor_sync(0xffffffffu, ls1, 2);
        l0 = l0 * c0 + ls0;
        l1 = l1 * c1 + ls1;

#pragma unroll
        for (int j = 0; j < 16; j++) { o0[j] *= c0; o1[j] *= c1; }

#pragma unroll
        for (int j = 0; j < 16; j++) {
            Ps[r * SSTRIDE + d0 + j]        = s0[j];
            Ps[(r + 64) * SSTRIDE + d0 + j] = s1[j];
        }
        __syncthreads();

        // PV accumulate: o[d0..d0+15] over 64 key columns
#pragma unroll 8
        for (int c = 0; c < 64; c++) {
            float p0 = Ps[r * SSTRIDE + c];
            float p1 = Ps[(r + 64) * SSTRIDE + c];
#pragma unroll
            for (int v4 = 0; v4 < 4; v4++) {
                float4 vv = *(const float4*)&Vs[c * SSTRIDE + d0 + v4 * 4];
                o0[v4*4+0] += p0 * vv.x; o0[v4*4+1] += p0 * vv.y;
                o0[v4*4+2] += p0 * vv.z; o0[v4*4+3] += p0 * vv.w;
                o1[v4*4+0] += p1 * vv.x; o1[v4*4+1] += p1 * vv.y;
                o1[v4*4+2] += p1 * vv.z; o1[v4*4+3] += p1 * vv.w;
            }
        }
    }

    // Finalize and write ctx in [B, L, E] layout (e = h*64 + d)
    const int b = bh >> 4;     // bh / 16
    const int h = bh & 15;
    float inv0 = 1.f / l0;
    float inv1 = 1.f / l1;
    float* C0 = g_ctx + ((size_t)b * LSEQ + q0 + r) * EMB + h * DH + d0;
    float* C1 = g_ctx + ((size_t)b * LSEQ + q0 + r + 64) * EMB + h * DH + d0;
#pragma unroll
    for (int j = 0; j < 16; j++) {
        C0[j] = o0[j] * inv0;
        C1[j] = o1[j] * inv1;
    }
}

// ---------------------------------------------------------------------------
extern "C" void kernel_launch(void* const* d_in, const int* in_sizes, int n_in,
                              void* d_out, int out_size)
{
    const float* X     = (const float*)d_in[0];
    const float* keb   = (const float*)d_in[1];
    const float* w_in  = (const float*)d_in[2];
    const float* b_in  = (const float*)d_in[3];
    const float* w_out = (const float*)d_in[4];
    const float* b_out = (const float*)d_in[5];
    float* out = (float*)d_out;

    cudaFuncSetAttribute(attn_kernel,
                         cudaFuncAttributeMaxDynamicSharedMemorySize, ATTN_SMEM);

    // 1) QKV projection, scatter to [BH, L, D]
    dim3 g1(N1 / 64, M1 / 128);
    gemm_tn_kernel<0><<<g1, 256>>>(X, w_in, b_in, nullptr, M1, N1, KDIM);

    // 2) Attention with additive ke_bias
    dim3 g2(LSEQ / 128, BH);
    attn_kernel<<<g2, 256, ATTN_SMEM>>>(keb);

    // 3) Output projection
    dim3 g3(EMB / 64, M1 / 128);
    gemm_tn_kernel<1><<<g3, 256>>>(nullptr, w_out, b_out, out, M1, EMB, KDIM);
}

// round 2
// speedup vs baseline: 4.7788x; 4.7788x over previous
#include <cuda_runtime.h>
#include <cuda_bf16.h>
#include <math.h>
#include <stdint.h>

// Problem constants
#define BSZ 2
#define LSEQ 2048
#define EMB 1024
#define NH 16
#define DH 64
#define BH 32          // BSZ*NH
#define M1 4096        // BSZ*LSEQ
#define N1 3072        // 3*EMB

// Scratch: Q/K/V as bf16 hi/lo in [BH, L, D]; ctx as bf16 hi/lo in [B, L, E]
__device__ __nv_bfloat16 g_qh[BH*LSEQ*DH];
__device__ __nv_bfloat16 g_ql[BH*LSEQ*DH];
__device__ __nv_bfloat16 g_kh[BH*LSEQ*DH];
__device__ __nv_bfloat16 g_kl[BH*LSEQ*DH];
__device__ __nv_bfloat16 g_vh[BH*LSEQ*DH];
__device__ __nv_bfloat16 g_vl[BH*LSEQ*DH];
__device__ __nv_bfloat16 g_ch[M1*EMB];
__device__ __nv_bfloat16 g_cl[M1*EMB];

// ---------------------------------------------------------------------------
// PTX helpers
// ---------------------------------------------------------------------------
__device__ __forceinline__ uint32_t smem_u32(const void* p) {
    return (uint32_t)__cvta_generic_to_shared(p);
}
__device__ __forceinline__ void ldm_x4(uint32_t& a0, uint32_t& a1,
                                       uint32_t& a2, uint32_t& a3, uint32_t addr) {
    asm volatile("ldmatrix.sync.aligned.m8n8.x4.shared.b16 {%0,%1,%2,%3},[%4];\n"
                 : "=r"(a0), "=r"(a1), "=r"(a2), "=r"(a3) : "r"(addr));
}
__device__ __forceinline__ void ldm_x4_t(uint32_t& a0, uint32_t& a1,
                                         uint32_t& a2, uint32_t& a3, uint32_t addr) {
    asm volatile("ldmatrix.sync.aligned.m8n8.x4.trans.shared.b16 {%0,%1,%2,%3},[%4];\n"
                 : "=r"(a0), "=r"(a1), "=r"(a2), "=r"(a3) : "r"(addr));
}
__device__ __forceinline__ void mma16816(float* c, const uint32_t* a,
                                         uint32_t b0, uint32_t b1) {
    asm volatile("mma.sync.aligned.m16n8k16.row.col.f32.bf16.bf16.f32 "
                 "{%0,%1,%2,%3},{%4,%5,%6,%7},{%8,%9},{%0,%1,%2,%3};\n"
                 : "+f"(c[0]), "+f"(c[1]), "+f"(c[2]), "+f"(c[3])
                 : "r"(a[0]), "r"(a[1]), "r"(a[2]), "r"(a[3]), "r"(b0), "r"(b1));
}

// ---------------------------------------------------------------------------
// GEMM: C[M,N] = A[M,1024] @ W[N,1024]^T + bias[N], split-bf16 3-pass mma.
// 256 threads (8 warps, 4m x 2n), BM=128, BN=64, BK=32.
// MODE 0: A = X (fp32, convert inline); epilogue scatters q/k/v (q pre-scaled)
//         as bf16 hi/lo into [BH, L, D] layout.
// MODE 1: A = g_ch/g_cl (bf16 hi/lo, direct copy); epilogue writes fp32 C.
// ---------------------------------------------------------------------------
#define GST 40

template<int MODE>
__global__ __launch_bounds__(256)
void gemm_mma(const float* __restrict__ A32,
              const float* __restrict__ W32,
              const float* __restrict__ bias,
              float* __restrict__ Cout)
{
    __shared__ __nv_bfloat16 Ah[128*GST];
    __shared__ __nv_bfloat16 Al[128*GST];
    __shared__ __nv_bfloat16 Wh[64*GST];
    __shared__ __nv_bfloat16 Wl[64*GST];

    const int tid = threadIdx.x, lane = tid & 31, w = tid >> 5;
    const int wm = w >> 1, wn = w & 1;
    const int m0 = blockIdx.y * 128, n0 = blockIdx.x * 64;

    float c[2][4][4];
#pragma unroll
    for (int a = 0; a < 2; a++)
#pragma unroll
        for (int b = 0; b < 4; b++)
#pragma unroll
            for (int d = 0; d < 4; d++) c[a][b][d] = 0.f;

    for (int k0 = 0; k0 < 1024; k0 += 32) {
        __syncthreads();
        if (MODE == 0) {
#pragma unroll
            for (int i = 0; i < 4; i++) {
                int id = tid + i * 256;
                int r = id >> 3, kc = (id & 7) * 4;
                float4 v = *(const float4*)(A32 + (size_t)(m0 + r) * 1024 + k0 + kc);
                __nv_bfloat16 h0 = __float2bfloat16(v.x);
                __nv_bfloat16 h1 = __float2bfloat16(v.y);
                __nv_bfloat16 h2 = __float2bfloat16(v.z);
                __nv_bfloat16 h3 = __float2bfloat16(v.w);
                __nv_bfloat16 l0 = __float2bfloat16(v.x - __bfloat162float(h0));
                __nv_bfloat16 l1 = __float2bfloat16(v.y - __bfloat162float(h1));
                __nv_bfloat16 l2 = __float2bfloat16(v.z - __bfloat162float(h2));
                __nv_bfloat16 l3 = __float2bfloat16(v.w - __bfloat162float(h3));
                __nv_bfloat162* ph = (__nv_bfloat162*)&Ah[r * GST + kc];
                ph[0] = __nv_bfloat162(h0, h1); ph[1] = __nv_bfloat162(h2, h3);
                __nv_bfloat162* pl = (__nv_bfloat162*)&Al[r * GST + kc];
                pl[0] = __nv_bfloat162(l0, l1); pl[1] = __nv_bfloat162(l2, l3);
            }
        } else {
#pragma unroll
            for (int i = 0; i < 2; i++) {
                int id = tid + i * 256;
                int r = id >> 2, kc = (id & 3) * 8;
                size_t src = (size_t)(m0 + r) * 1024 + k0 + kc;
                *(uint4*)&Ah[r * GST + kc] = *(const uint4*)(g_ch + src);
                *(uint4*)&Al[r * GST + kc] = *(const uint4*)(g_cl + src);
            }
        }
#pragma unroll
        for (int i = 0; i < 2; i++) {
            int id = tid + i * 256;
            int r = id >> 3, kc = (id & 7) * 4;
            float4 v = *(const float4*)(W32 + (size_t)(n0 + r) * 1024 + k0 + kc);
            __nv_bfloat16 h0 = __float2bfloat16(v.x);
            __nv_bfloat16 h1 = __float2bfloat16(v.y);
            __nv_bfloat16 h2 = __float2bfloat16(v.z);
            __nv_bfloat16 h3 = __float2bfloat16(v.w);
            __nv_bfloat16 l0 = __float2bfloat16(v.x - __bfloat162float(h0));
            __nv_bfloat16 l1 = __float2bfloat16(v.y - __bfloat162float(h1));
            __nv_bfloat16 l2 = __float2bfloat16(v.z - __bfloat162float(h2));
            __nv_bfloat16 l3 = __float2bfloat16(v.w - __bfloat162float(h3));
            __nv_bfloat162* ph = (__nv_bfloat162*)&Wh[r * GST + kc];
            ph[0] = __nv_bfloat162(h0, h1); ph[1] = __nv_bfloat162(h2, h3);
            __nv_bfloat162* pl = (__nv_bfloat162*)&Wl[r * GST + kc];
            pl[0] = __nv_bfloat162(l0, l1); pl[1] = __nv_bfloat162(l2, l3);
        }
        __syncthreads();

#pragma unroll
        for (int kk = 0; kk < 2; kk++) {
            uint32_t aH[2][4], aL[2][4];
#pragma unroll
            for (int mt = 0; mt < 2; mt++) {
                int row = wm * 32 + mt * 16 + (lane & 15);
                int kof = kk * 16 + ((lane >> 4) << 3);
                ldm_x4(aH[mt][0], aH[mt][1], aH[mt][2], aH[mt][3],
                       smem_u32(&Ah[row * GST + kof]));
                ldm_x4(aL[mt][0], aL[mt][1], aL[mt][2], aL[mt][3],
                       smem_u32(&Al[row * GST + kof]));
            }
#pragma unroll
            for (int np = 0; np < 2; np++) {
                int row = wn * 32 + np * 16 + ((lane >> 4) << 3) + (lane & 7);
                int kof = kk * 16 + ((lane >> 3) & 1) * 8;
                uint32_t bh0, bh1, bh2, bh3, bl0, bl1, bl2, bl3;
                ldm_x4(bh0, bh1, bh2, bh3, smem_u32(&Wh[row * GST + kof]));
                ldm_x4(bl0, bl1, bl2, bl3, smem_u32(&Wl[row * GST + kof]));
#pragma unroll
                for (int mt = 0; mt < 2; mt++) {
                    mma16816(c[mt][2*np],   aH[mt], bh0, bh1);
                    mma16816(c[mt][2*np+1], aH[mt], bh2, bh3);
                    mma16816(c[mt][2*np],   aH[mt], bl0, bl1);
                    mma16816(c[mt][2*np+1], aH[mt], bl2, bl3);
                    mma16816(c[mt][2*np],   aL[mt], bh0, bh1);
                    mma16816(c[mt][2*np+1], aL[mt], bh2, bh3);
                }
            }
        }
    }

    // Epilogue
    const int rA = lane >> 2, colq = (lane & 3) * 2;
#pragma unroll
    for (int mt = 0; mt < 2; mt++) {
#pragma unroll
        for (int nt = 0; nt < 4; nt++) {
            int n = n0 + wn * 32 + nt * 8 + colq;
            int mrow = m0 + wm * 32 + mt * 16 + rA;
            float bv0 = bias[n], bv1 = bias[n + 1];
            float v0 = c[mt][nt][0] + bv0, v1 = c[mt][nt][1] + bv1;
            float v2 = c[mt][nt][2] + bv0, v3 = c[mt][nt][3] + bv1;
            if (MODE == 0) {
                int which = n >> 10;
                int e = n & 1023, hh = e >> 6, d = e & 63;
                if (which == 0) { v0 *= 0.125f; v1 *= 0.125f; v2 *= 0.125f; v3 *= 0.125f; }
                int b = mrow >> 11;
                size_t dA = (((size_t)(b * NH + hh)) * LSEQ + (mrow & 2047)) * DH + d;
                size_t dB = (((size_t)(b * NH + hh)) * LSEQ + ((mrow + 8) & 2047)) * DH + d;
                __nv_bfloat16 h0 = __float2bfloat16(v0);
                __nv_bfloat16 h1 = __float2bfloat16(v1);
                __nv_bfloat16 h2 = __float2bfloat16(v2);
                __nv_bfloat16 h3 = __float2bfloat16(v3);
                __nv_bfloat16 l0 = __float2bfloat16(v0 - __bfloat162float(h0));
                __nv_bfloat16 l1 = __float2bfloat16(v1 - __bfloat162float(h1));
                __nv_bfloat16 l2 = __float2bfloat16(v2 - __bfloat162float(h2));
                __nv_bfloat16 l3 = __float2bfloat16(v3 - __bfloat162float(h3));
                __nv_bfloat16 *dh, *dl;
                if (which == 0)      { dh = g_qh; dl = g_ql; }
                else if (which == 1) { dh = g_kh; dl = g_kl; }
                else                 { dh = g_vh; dl = g_vl; }
                *(__nv_bfloat162*)(dh + dA) = __nv_bfloat162(h0, h1);
                *(__nv_bfloat162*)(dl + dA) = __nv_bfloat162(l0, l1);
                *(__nv_bfloat162*)(dh + dB) = __nv_bfloat162(h2, h3);
                *(__nv_bfloat162*)(dl + dB) = __nv_bfloat162(l2, l3);
            } else {
                *(float2*)(Cout + (size_t)mrow * EMB + n) = make_float2(v0, v1);
                *(float2*)(Cout + (size_t)(mrow + 8) * EMB + n) = make_float2(v2, v3);
            }
        }
    }
}

// ---------------------------------------------------------------------------
// Flash attention with additive bias, split-bf16 mma.
// Grid (L/128, BH), 256 threads (8 warps). Br=128 (warp owns 16 rows), Bc=64.
// ---------------------------------------------------------------------------
#define AST 72
#define ATTN_SMEM ((size_t)(128+64+64+128)*AST*2*sizeof(__nv_bfloat16))  // 110592

__global__ __launch_bounds__(256)
void attn_mma(const float* __restrict__ keb)
{
    extern __shared__ __nv_bfloat16 sm[];
    __nv_bfloat16 *Qh = sm,            *Ql = Qh + 128*AST,
                  *Kh = Ql + 128*AST,  *Kl = Kh + 64*AST,
                  *Vh = Kl + 64*AST,   *Vl = Vh + 64*AST,
                  *Ph = Vl + 64*AST,   *Pl = Ph + 128*AST;

    const int tid = threadIdx.x, lane = tid & 31, w = tid >> 5;
    const int bh = blockIdx.y;
    const int q0 = blockIdx.x * 128;
    const size_t hb = (size_t)bh * LSEQ * DH;
    const float* Bg = keb + (size_t)bh * LSEQ * LSEQ;

    // Q tile -> smem
#pragma unroll
    for (int i = 0; i < 4; i++) {
        int id = tid + i * 256;
        int r = id >> 3, c8 = (id & 7) * 8;
        size_t src = hb + (size_t)(q0 + r) * DH + c8;
        *(uint4*)&Qh[r * AST + c8] = *(const uint4*)(g_qh + src);
        *(uint4*)&Ql[r * AST + c8] = *(const uint4*)(g_ql + src);
    }
    __syncthreads();

    // Q fragments held in registers for the whole kv loop
    uint32_t qH[4][4], qL[4][4];
#pragma unroll
    for (int kk = 0; kk < 4; kk++) {
        int row = w * 16 + (lane & 15);
        int kof = kk * 16 + ((lane >> 4) << 3);
        ldm_x4(qH[kk][0], qH[kk][1], qH[kk][2], qH[kk][3], smem_u32(&Qh[row * AST + kof]));
        ldm_x4(qL[kk][0], qL[kk][1], qL[kk][2], qL[kk][3], smem_u32(&Ql[row * AST + kof]));
    }

    float o[8][4];
#pragma unroll
    for (int j = 0; j < 8; j++)
#pragma unroll
        for (int d = 0; d < 4; d++) o[j][d] = 0.f;
    float mA = -INFINITY, mB = -INFINITY, lA = 0.f, lB = 0.f;

    const int rA = lane >> 2, colq = (lane & 3) * 2;
    const int qrowA = q0 + w * 16 + rA;

    for (int k0 = 0; k0 < LSEQ; k0 += 64) {
        __syncthreads();
#pragma unroll
        for (int i = 0; i < 2; i++) {
            int id = tid + i * 256;
            int r = id >> 3, c8 = (id & 7) * 8;
            size_t src = hb + (size_t)(k0 + r) * DH + c8;
            *(uint4*)&Kh[r * AST + c8] = *(const uint4*)(g_kh + src);
            *(uint4*)&Kl[r * AST + c8] = *(const uint4*)(g_kl + src);
            *(uint4*)&Vh[r * AST + c8] = *(const uint4*)(g_vh + src);
            *(uint4*)&Vl[r * AST + c8] = *(const uint4*)(g_vl + src);
        }
        __syncthreads();

        // S init = bias
        float s[8][4];
#pragma unroll
        for (int j = 0; j < 8; j++) {
            float2 b0 = *(const float2*)(Bg + (size_t)qrowA * LSEQ + k0 + j * 8 + colq);
            float2 b1 = *(const float2*)(Bg + (size_t)(qrowA + 8) * LSEQ + k0 + j * 8 + colq);
            s[j][0] = b0.x; s[j][1] = b0.y; s[j][2] = b1.x; s[j][3] = b1.y;
        }

        // S += Q K^T (3-pass split bf16)
#pragma unroll
        for (int kk = 0; kk < 4; kk++) {
#pragma unroll
            for (int np = 0; np < 4; np++) {
                int row = np * 16 + ((lane >> 4) << 3) + (lane & 7);
                int kof = kk * 16 + ((lane >> 3) & 1) * 8;
                uint32_t bh0, bh1, bh2, bh3, bl0, bl1, bl2, bl3;
                ldm_x4(bh0, bh1, bh2, bh3, smem_u32(&Kh[row * AST + kof]));
                ldm_x4(bl0, bl1, bl2, bl3, smem_u32(&Kl[row * AST + kof]));
                mma16816(s[2*np],   qH[kk], bh0, bh1);
                mma16816(s[2*np+1], qH[kk], bh2, bh3);
                mma16816(s[2*np],   qH[kk], bl0, bl1);
                mma16816(s[2*np+1], qH[kk], bl2, bl3);
                mma16816(s[2*np],   qL[kk], bh0, bh1);
                mma16816(s[2*np+1], qL[kk], bh2, bh3);
            }
        }

        // online softmax
        float mxA = -INFINITY, mxB = -INFINITY;
#pragma unroll
        for (int j = 0; j < 8; j++) {
            mxA = fmaxf(mxA, fmaxf(s[j][0], s[j][1]));
            mxB = fmaxf(mxB, fmaxf(s[j][2], s[j][3]));
        }
        mxA = fmaxf(mxA, __shfl_xor_sync(0xffffffffu, mxA, 1));
        mxA = fmaxf(mxA, __shfl_xor_sync(0xffffffffu, mxA, 2));
        mxB = fmaxf(mxB, __shfl_xor_sync(0xffffffffu, mxB, 1));
        mxB = fmaxf(mxB, __shfl_xor_sync(0xffffffffu, mxB, 2));

        float mnA = fmaxf(mA, mxA), mnB = fmaxf(mB, mxB);
        float cA = __expf(mA - mnA), cB = __expf(mB - mnB);
        mA = mnA; mB = mnB;

        float sA = 0.f, sB = 0.f;
#pragma unroll
        for (int j = 0; j < 8; j++) {
            float p0 = __expf(s[j][0] - mnA);
            float p1 = __expf(s[j][1] - mnA);
            float p2 = __expf(s[j][2] - mnB);
            float p3 = __expf(s[j][3] - mnB);
            sA += p0 + p1; sB += p2 + p3;
            __nv_bfloat16 h0 = __float2bfloat16(p0);
            __nv_bfloat16 h1 = __float2bfloat16(p1);
            __nv_bfloat16 h2 = __float2bfloat16(p2);
            __nv_bfloat16 h3 = __float2bfloat16(p3);
            __nv_bfloat16 l0 = __float2bfloat16(p0 - __bfloat162float(h0));
            __nv_bfloat16 l1 = __float2bfloat16(p1 - __bfloat162float(h1));
            __nv_bfloat16 l2 = __float2bfloat16(p2 - __bfloat162float(h2));
            __nv_bfloat16 l3 = __float2bfloat16(p3 - __bfloat162float(h3));
            int col = j * 8 + colq;
            *(__nv_bfloat162*)&Ph[(w*16 + rA) * AST + col]     = __nv_bfloat162(h0, h1);
            *(__nv_bfloat162*)&Pl[(w*16 + rA) * AST + col]     = __nv_bfloat162(l0, l1);
            *(__nv_bfloat162*)&Ph[(w*16 + rA + 8) * AST + col] = __nv_bfloat162(h2, h3);
            *(__nv_bfloat162*)&Pl[(w*16 + rA + 8) * AST + col] = __nv_bfloat162(l2, l3);
        }
        sA += __shfl_xor_sync(0xffffffffu, sA, 1);
        sA += __shfl_xor_sync(0xffffffffu, sA, 2);
        sB += __shfl_xor_sync(0xffffffffu, sB, 1);
        sB += __shfl_xor_sync(0xffffffffu, sB, 2);
        lA = lA * cA + sA;
        lB = lB * cB + sB;

#pragma unroll
        for (int j = 0; j < 8; j++) {
            o[j][0] *= cA; o[j][1] *= cA; o[j][2] *= cB; o[j][3] *= cB;
        }
        __syncwarp();

        // O += P V (3-pass split bf16); B frag via ldmatrix.trans on V[k][d]
#pragma unroll
        for (int kk = 0; kk < 4; kk++) {
            uint32_t pH[4], pL[4];
            int prow = w * 16 + (lane & 15);
            int pkof = kk * 16 + ((lane >> 4) << 3);
            ldm_x4(pH[0], pH[1], pH[2], pH[3], smem_u32(&Ph[prow * AST + pkof]));
            ldm_x4(pL[0], pL[1], pL[2], pL[3], smem_u32(&Pl[prow * AST + pkof]));
#pragma unroll
            for (int np = 0; np < 4; np++) {
                int vrow = kk * 16 + ((lane >> 3) & 1) * 8 + (lane & 7);
                int vcol = np * 16 + (lane >> 4) * 8;
                uint32_t vh0, vh1, vh2, vh3, vl0, vl1, vl2, vl3;
                ldm_x4_t(vh0, vh1, vh2, vh3, smem_u32(&Vh[vrow * AST + vcol]));
                ldm_x4_t(vl0, vl1, vl2, vl3, smem_u32(&Vl[vrow * AST + vcol]));
                mma16816(o[2*np],   pH, vh0, vh1);
                mma16816(o[2*np+1], pH, vh2, vh3);
                mma16816(o[2*np],   pH, vl0, vl1);
                mma16816(o[2*np+1], pH, vl2, vl3);
                mma16816(o[2*np],   pL, vh0, vh1);
                mma16816(o[2*np+1], pL, vh2, vh3);
            }
        }
    }

    // Epilogue: ctx as bf16 hi/lo in [B, L, E]
    const float invA = 1.f / lA, invB = 1.f / lB;
    const int b = bh >> 4, h = bh & 15;
#pragma unroll
    for (int j = 0; j < 8; j++) {
        int d = j * 8 + colq;
        size_t eA = ((size_t)b * LSEQ + qrowA) * EMB + h * 64 + d;
        size_t eB = eA + (size_t)8 * EMB;
        float v0 = o[j][0] * invA, v1 = o[j][1] * invA;
        float v2 = o[j][2] * invB, v3 = o[j][3] * invB;
        __nv_bfloat16 h0 = __float2bfloat16(v0);
        __nv_bfloat16 h1 = __float2bfloat16(v1);
        __nv_bfloat16 h2 = __float2bfloat16(v2);
        __nv_bfloat16 h3 = __float2bfloat16(v3);
        __nv_bfloat16 l0 = __float2bfloat16(v0 - __bfloat162float(h0));
        __nv_bfloat16 l1 = __float2bfloat16(v1 - __bfloat162float(h1));
        __nv_bfloat16 l2 = __float2bfloat16(v2 - __bfloat162float(h2));
        __nv_bfloat16 l3 = __float2bfloat16(v3 - __bfloat162float(h3));
        *(__nv_bfloat162*)(g_ch + eA) = __nv_bfloat162(h0, h1);
        *(__nv_bfloat162*)(g_cl + eA) = __nv_bfloat162(l0, l1);
        *(__nv_bfloat162*)(g_ch + eB) = __nv_bfloat162(h2, h3);
        *(__nv_bfloat162*)(g_cl + eB) = __nv_bfloat162(l2, l3);
    }
}

// ---------------------------------------------------------------------------
extern "C" void kernel_launch(void* const* d_in, const int* in_sizes, int n_in,
                              void* d_out, int out_size)
{
    const float* X     = (const float*)d_in[0];
    const float* keb   = (const float*)d_in[1];
    const float* w_in  = (const float*)d_in[2];
    const float* b_in  = (const float*)d_in[3];
    const float* w_out = (const float*)d_in[4];
    const float* b_out = (const float*)d_in[5];
    float* out = (float*)d_out;

    cudaFuncSetAttribute(attn_mma,
                         cudaFuncAttributeMaxDynamicSharedMemorySize, (int)ATTN_SMEM);

    // 1) QKV projection -> bf16 hi/lo Q(K scaled)/K/V in [BH, L, D]
    gemm_mma<0><<<dim3(N1/64, M1/128), 256>>>(X, w_in, b_in, nullptr);

    // 2) Attention with additive ke_bias -> ctx bf16 hi/lo [B, L, E]
    attn_mma<<<dim3(LSEQ/128, BH), 256, ATTN_SMEM>>>(keb);

    // 3) Output projection (fp32 out)
    gemm_mma<1><<<dim3(EMB/64, M1/128), 256>>>(nullptr, w_out, b_out, out);
}

// round 4
// speedup vs baseline: 5.1184x; 1.0711x over previous
#include <cuda_runtime.h>
#include <cuda_bf16.h>
#include <math.h>
#include <stdint.h>

// Problem constants
#define BSZ 2
#define LSEQ 2048
#define EMB 1024
#define NH 16
#define DH 64
#define BH 32          // BSZ*NH
#define M1 4096        // BSZ*LSEQ
#define N1 3072        // 3*EMB

// Scratch (allocation-free)
__device__ __nv_bfloat16 g_xh[M1*EMB],  g_xl[M1*EMB];
__device__ __nv_bfloat16 g_wih[N1*EMB], g_wil[N1*EMB];
__device__ __nv_bfloat16 g_woh[EMB*EMB],g_wol[EMB*EMB];
__device__ __nv_bfloat16 g_qh[BH*LSEQ*DH], g_ql[BH*LSEQ*DH];
__device__ __nv_bfloat16 g_kh[BH*LSEQ*DH], g_kl[BH*LSEQ*DH];
__device__ __nv_bfloat16 g_vh[BH*LSEQ*DH], g_vl[BH*LSEQ*DH];
__device__ __nv_bfloat16 g_ch[M1*EMB],  g_cl[M1*EMB];

// ---------------------------------------------------------------------------
// PTX helpers
// ---------------------------------------------------------------------------
__device__ __forceinline__ uint32_t smem_u32(const void* p) {
    return (uint32_t)__cvta_generic_to_shared(p);
}
__device__ __forceinline__ void ldm_x4(uint32_t& a0, uint32_t& a1,
                                       uint32_t& a2, uint32_t& a3, uint32_t addr) {
    asm volatile("ldmatrix.sync.aligned.m8n8.x4.shared.b16 {%0,%1,%2,%3},[%4];\n"
                 : "=r"(a0), "=r"(a1), "=r"(a2), "=r"(a3) : "r"(addr));
}
__device__ __forceinline__ void ldm_x4_t(uint32_t& a0, uint32_t& a1,
                                         uint32_t& a2, uint32_t& a3, uint32_t addr) {
    asm volatile("ldmatrix.sync.aligned.m8n8.x4.trans.shared.b16 {%0,%1,%2,%3},[%4];\n"
                 : "=r"(a0), "=r"(a1), "=r"(a2), "=r"(a3) : "r"(addr));
}
__device__ __forceinline__ void mma16816(float* c, const uint32_t* a,
                                         uint32_t b0, uint32_t b1) {
    asm volatile("mma.sync.aligned.m16n8k16.row.col.f32.bf16.bf16.f32 "
                 "{%0,%1,%2,%3},{%4,%5,%6,%7},{%8,%9},{%0,%1,%2,%3};\n"
                 : "+f"(c[0]), "+f"(c[1]), "+f"(c[2]), "+f"(c[3])
                 : "r"(a[0]), "r"(a[1]), "r"(a[2]), "r"(a[3]), "r"(b0), "r"(b1));
}
__device__ __forceinline__ void cp16(void* smem_ptr, const void* gptr) {
    asm volatile("cp.async.cg.shared.global [%0], [%1], 16;\n"
                 :: "r"(smem_u32(smem_ptr)), "l"(gptr));
}
__device__ __forceinline__ void cp_commit() {
    asm volatile("cp.async.commit_group;\n");
}
__device__ __forceinline__ void cp_wait0() {
    asm volatile("cp.async.wait_group 0;\n");
}
__device__ __forceinline__ uint32_t packbf(float lo, float hi) {
    uint32_t r;
    asm("cvt.rn.bf16x2.f32 %0, %1, %2;" : "=r"(r) : "f"(hi), "f"(lo));
    return r;
}
// pack hi and residual-lo bf16x2 from two fp32 values
__device__ __forceinline__ void pack_hilo(float v0, float v1,
                                          uint32_t& ph, uint32_t& pl) {
    ph = packbf(v0, v1);
    __nv_bfloat162 h = *(__nv_bfloat162*)&ph;
    pl = packbf(v0 - __bfloat162float(h.x), v1 - __bfloat162float(h.y));
}

// ---------------------------------------------------------------------------
// Prep: fp32 -> bf16 hi/lo split
// ---------------------------------------------------------------------------
__global__ __launch_bounds__(256)
void cvt_hilo(const float* __restrict__ src, int sel, int n4)
{
    int i = blockIdx.x * 256 + threadIdx.x;
    if (i >= n4) return;
    __nv_bfloat16 *dh, *dl;
    if (sel == 0)      { dh = g_xh;  dl = g_xl;  }
    else if (sel == 1) { dh = g_wih; dl = g_wil; }
    else               { dh = g_woh; dl = g_wol; }
    float4 v = ((const float4*)src)[i];
    __nv_bfloat16 h0 = __float2bfloat16(v.x);
    __nv_bfloat16 h1 = __float2bfloat16(v.y);
    __nv_bfloat16 h2 = __float2bfloat16(v.z);
    __nv_bfloat16 h3 = __float2bfloat16(v.w);
    __nv_bfloat16 l0 = __float2bfloat16(v.x - __bfloat162float(h0));
    __nv_bfloat16 l1 = __float2bfloat16(v.y - __bfloat162float(h1));
    __nv_bfloat16 l2 = __float2bfloat16(v.z - __bfloat162float(h2));
    __nv_bfloat16 l3 = __float2bfloat16(v.w - __bfloat162float(h3));
    ((__nv_bfloat162*)dh)[2*i]   = __nv_bfloat162(h0, h1);
    ((__nv_bfloat162*)dh)[2*i+1] = __nv_bfloat162(h2, h3);
    ((__nv_bfloat162*)dl)[2*i]   = __nv_bfloat162(l0, l1);
    ((__nv_bfloat162*)dl)[2*i+1] = __nv_bfloat162(l2, l3);
}

// ---------------------------------------------------------------------------
// GEMM: C[M,N] = A @ W^T + bias. Split-bf16 3-pass mma, cp.async double buffer.
// BM=128, BN=128, BK=32, 256 threads (8 warps: 4m x 2n, warp = 32m x 64n).
// MODE 0: A=g_x*, W=g_wi*; epilogue scatters q(scaled)/k/v hi/lo -> [BH,L,D]
// MODE 1: A=g_c*, W=g_wo*; epilogue writes fp32 C row-major
// ---------------------------------------------------------------------------
#define GST 40
#define GARR 5120           // 128*GST
#define GSTAGE 20480        // 4 arrays per stage
#define GEMM_SMEM (2*GSTAGE*2)  // bytes = 81920

template<int MODE>
__global__ __launch_bounds__(256, 2)
void gemm_mma(const float* __restrict__ bias, float* __restrict__ Cout)
{
    extern __shared__ __nv_bfloat16 smg[];
    const int tid = threadIdx.x, lane = tid & 31, w = tid >> 5;
    const int wm = w >> 1, wn = w & 1;
    const int m0 = blockIdx.y * 128, n0 = blockIdx.x * 128;

    const __nv_bfloat16* Ahg = (MODE == 0) ? g_xh  : g_ch;
    const __nv_bfloat16* Alg = (MODE == 0) ? g_xl  : g_cl;
    const __nv_bfloat16* Whg = (MODE == 0) ? g_wih : g_woh;
    const __nv_bfloat16* Wlg = (MODE == 0) ? g_wil : g_wol;

    const int lr = tid >> 1;            // 0..127
    const int lq = (tid & 1) * 16;      // elem offset 0/16
    const __nv_bfloat16* pAh = Ahg + (size_t)(m0 + lr) * 1024 + lq;
    const __nv_bfloat16* pAl = Alg + (size_t)(m0 + lr) * 1024 + lq;
    const __nv_bfloat16* pWh = Whg + (size_t)(n0 + lr) * 1024 + lq;
    const __nv_bfloat16* pWl = Wlg + (size_t)(n0 + lr) * 1024 + lq;

    auto load_stage = [&](int st, int k0) {
        __nv_bfloat16* b = smg + st * GSTAGE + lr * GST + lq;
        cp16(b,            pAh + k0); cp16(b + 8,          pAh + k0 + 8);
        cp16(b + GARR,     pAl + k0); cp16(b + GARR + 8,   pAl + k0 + 8);
        cp16(b + 2*GARR,   pWh + k0); cp16(b + 2*GARR + 8, pWh + k0 + 8);
        cp16(b + 3*GARR,   pWl + k0); cp16(b + 3*GARR + 8, pWl + k0 + 8);
        cp_commit();
    };

    float c[2][8][4];
#pragma unroll
    for (int a = 0; a < 2; a++)
#pragma unroll
        for (int b = 0; b < 8; b++)
#pragma unroll
            for (int d = 0; d < 4; d++) c[a][b][d] = 0.f;

    load_stage(0, 0);

    for (int it = 0; it < 32; it++) {
        cp_wait0();
        __syncthreads();
        if (it < 31) load_stage((it + 1) & 1, (it + 1) * 32);

        __nv_bfloat16* Ah = smg + (it & 1) * GSTAGE;
        __nv_bfloat16* Al = Ah + GARR;
        __nv_bfloat16* Wh = Ah + 2*GARR;
        __nv_bfloat16* Wl = Ah + 3*GARR;

#pragma unroll
        for (int kk = 0; kk < 2; kk++) {
            uint32_t aH[2][4], aL[2][4];
#pragma unroll
            for (int mt = 0; mt < 2; mt++) {
                int row = wm * 32 + mt * 16 + (lane & 15);
                int kof = kk * 16 + ((lane >> 4) << 3);
                ldm_x4(aH[mt][0], aH[mt][1], aH[mt][2], aH[mt][3],
                       smem_u32(&Ah[row * GST + kof]));
                ldm_x4(aL[mt][0], aL[mt][1], aL[mt][2], aL[mt][3],
                       smem_u32(&Al[row * GST + kof]));
            }
#pragma unroll
            for (int np = 0; np < 4; np++) {
                int row = wn * 64 + np * 16 + ((lane >> 4) << 3) + (lane & 7);
                int kof = kk * 16 + ((lane >> 3) & 1) * 8;
                uint32_t bh0, bh1, bh2, bh3, bl0, bl1, bl2, bl3;
                ldm_x4(bh0, bh1, bh2, bh3, smem_u32(&Wh[row * GST + kof]));
                ldm_x4(bl0, bl1, bl2, bl3, smem_u32(&Wl[row * GST + kof]));
#pragma unroll
                for (int mt = 0; mt < 2; mt++) {
                    mma16816(c[mt][2*np],   aH[mt], bh0, bh1);
                    mma16816(c[mt][2*np+1], aH[mt], bh2, bh3);
                    mma16816(c[mt][2*np],   aH[mt], bl0, bl1);
                    mma16816(c[mt][2*np+1], aH[mt], bl2, bl3);
                    mma16816(c[mt][2*np],   aL[mt], bh0, bh1);
                    mma16816(c[mt][2*np+1], aL[mt], bh2, bh3);
                }
            }
        }
    }

    // Epilogue
    const int rA = lane >> 2, colq = (lane & 3) * 2;
#pragma unroll
    for (int mt = 0; mt < 2; mt++) {
#pragma unroll
        for (int np = 0; np < 4; np++) {
#pragma unroll
            for (int cc = 0; cc < 2; cc++) {
                int n = n0 + wn * 64 + np * 16 + cc * 8 + colq;
                int mrow = m0 + wm * 32 + mt * 16 + rA;
                float bv0 = bias[n], bv1 = bias[n + 1];
                float* cp = c[mt][2*np + cc];
                float v0 = cp[0] + bv0, v1 = cp[1] + bv1;
                float v2 = cp[2] + bv0, v3 = cp[3] + bv1;
                if (MODE == 0) {
                    int which = n >> 10;
                    int e = n & 1023, hh = e >> 6, d = e & 63;
                    if (which == 0) { v0*=0.125f; v1*=0.125f; v2*=0.125f; v3*=0.125f; }
                    int b = mrow >> 11;
                    size_t dA = (((size_t)(b * NH + hh)) * LSEQ + (mrow & 2047)) * DH + d;
                    size_t dB = dA + 8 * DH;
                    __nv_bfloat16 h0 = __float2bfloat16(v0);
                    __nv_bfloat16 h1 = __float2bfloat16(v1);
                    __nv_bfloat16 h2 = __float2bfloat16(v2);
                    __nv_bfloat16 h3 = __float2bfloat16(v3);
                    __nv_bfloat16 l0 = __float2bfloat16(v0 - __bfloat162float(h0));
                    __nv_bfloat16 l1 = __float2bfloat16(v1 - __bfloat162float(h1));
                    __nv_bfloat16 l2 = __float2bfloat16(v2 - __bfloat162float(h2));
                    __nv_bfloat16 l3 = __float2bfloat16(v3 - __bfloat162float(h3));
                    __nv_bfloat16 *dh, *dl;
                    if (which == 0)      { dh = g_qh; dl = g_ql; }
                    else if (which == 1) { dh = g_kh; dl = g_kl; }
                    else                 { dh = g_vh; dl = g_vl; }
                    *(__nv_bfloat162*)(dh + dA) = __nv_bfloat162(h0, h1);
                    *(__nv_bfloat162*)(dl + dA) = __nv_bfloat162(l0, l1);
                    *(__nv_bfloat162*)(dh + dB) = __nv_bfloat162(h2, h3);
                    *(__nv_bfloat162*)(dl + dB) = __nv_bfloat162(l2, l3);
                } else {
                    *(float2*)(Cout + (size_t)mrow * EMB + n) = make_float2(v0, v1);
                    *(float2*)(Cout + (size_t)(mrow + 8) * EMB + n) = make_float2(v2, v3);
                }
            }
        }
    }
}

// ---------------------------------------------------------------------------
// Flash attention: QK 3-pass split bf16, PV 3-pass with register hi/lo P,
// K/V double-buffered via cp.async, bias prefetched into registers.
// Grid (L/128, BH), 256 threads. Br=128 (16 rows/warp), Bc=64.
// ---------------------------------------------------------------------------
#define AST 72
#define KARR 4608          // 64*AST
#define KSTAGE 18432       // 4 arrays
#define ATTN_SMEM 110592   // (2*9216 + 2*18432) elems * 2B

__global__ __launch_bounds__(256, 1)
void attn_mma(const float* __restrict__ keb)
{
    extern __shared__ __nv_bfloat16 sma[];
    __nv_bfloat16* Qh = sma;
    __nv_bfloat16* Ql = sma + 9216;
    __nv_bfloat16* KVbase = sma + 18432;

    const int tid = threadIdx.x, lane = tid & 31, w = tid >> 5;
    const int bh = blockIdx.y;
    const int q0 = blockIdx.x * 128;
    const size_t hb = (size_t)bh * LSEQ * DH;
    const float* Bg = keb + (size_t)bh * LSEQ * LSEQ;

    const int lr = tid >> 2;           // 0..63
    const int lq = (tid & 3) * 16;     // 0,16,32,48
    const __nv_bfloat16* pKh = g_kh + hb + (size_t)lr * 64 + lq;
    const __nv_bfloat16* pKl = g_kl + hb + (size_t)lr * 64 + lq;
    const __nv_bfloat16* pVh = g_vh + hb + (size_t)lr * 64 + lq;
    const __nv_bfloat16* pVl = g_vl + hb + (size_t)lr * 64 + lq;

    auto load_kv = [&](int st, int k0) {
        __nv_bfloat16* b = KVbase + st * KSTAGE + lr * AST + lq;
        size_t off = (size_t)k0 * 64;
        cp16(b,            pKh + off); cp16(b + 8,          pKh + off + 8);
        cp16(b + KARR,     pKl + off); cp16(b + KARR + 8,   pKl + off + 8);
        cp16(b + 2*KARR,   pVh + off); cp16(b + 2*KARR + 8, pVh + off + 8);
        cp16(b + 3*KARR,   pVl + off); cp16(b + 3*KARR + 8, pVl + off + 8);
        cp_commit();
    };

    load_kv(0, 0);

    // Q tile -> smem
#pragma unroll
    for (int i = 0; i < 4; i++) {
        int id = tid + i * 256;
        int r = id >> 3, c8 = (id & 7) * 8;
        size_t src = hb + (size_t)(q0 + r) * DH + c8;
        *(uint4*)&Qh[r * AST + c8] = *(const uint4*)(g_qh + src);
        *(uint4*)&Ql[r * AST + c8] = *(const uint4*)(g_ql + src);
    }
    __syncthreads();

    uint32_t qH[4][4], qL[4][4];
#pragma unroll
    for (int kk = 0; kk < 4; kk++) {
        int row = w * 16 + (lane & 15);
        int kof = kk * 16 + ((lane >> 4) << 3);
        ldm_x4(qH[kk][0], qH[kk][1], qH[kk][2], qH[kk][3], smem_u32(&Qh[row * AST + kof]));
        ldm_x4(qL[kk][0], qL[kk][1], qL[kk][2], qL[kk][3], smem_u32(&Ql[row * AST + kof]));
    }

    float o[8][4];
#pragma unroll
    for (int j = 0; j < 8; j++)
#pragma unroll
        for (int d = 0; d < 4; d++) o[j][d] = 0.f;
    float mA = -INFINITY, mB = -INFINITY, lA = 0.f, lB = 0.f;

    const int rA = lane >> 2, colq = (lane & 3) * 2;
    const int qrowA = q0 + w * 16 + rA;
    const float* Br0 = Bg + (size_t)qrowA * LSEQ + colq;
    const float* Br1 = Bg + (size_t)(qrowA + 8) * LSEQ + colq;

    for (int it = 0; it < 32; it++) {
        const int k0 = it * 64;
        cp_wait0();
        __syncthreads();

        float2 bb0[8], bb1[8];
#pragma unroll
        for (int j = 0; j < 8; j++) {
            bb0[j] = *(const float2*)(Br0 + k0 + j * 8);
            bb1[j] = *(const float2*)(Br1 + k0 + j * 8);
        }

        if (it < 31) load_kv((it + 1) & 1, k0 + 64);

        __nv_bfloat16* Kh = KVbase + (it & 1) * KSTAGE;
        __nv_bfloat16* Kl = Kh + KARR;
        __nv_bfloat16* Vh = Kh + 2*KARR;
        __nv_bfloat16* Vl = Kh + 3*KARR;

        float s[8][4];
#pragma unroll
        for (int j = 0; j < 8; j++)
#pragma unroll
            for (int d = 0; d < 4; d++) s[j][d] = 0.f;

        // S = Q K^T (3-pass)
#pragma unroll
        for (int kk = 0; kk < 4; kk++) {
#pragma unroll
            for (int np = 0; np < 4; np++) {
                int row = np * 16 + ((lane >> 4) << 3) + (lane & 7);
                int kof = kk * 16 + ((lane >> 3) & 1) * 8;
                uint32_t bh0, bh1, bh2, bh3, bl0, bl1, bl2, bl3;
                ldm_x4(bh0, bh1, bh2, bh3, smem_u32(&Kh[row * AST + kof]));
                ldm_x4(bl0, bl1, bl2, bl3, smem_u32(&Kl[row * AST + kof]));
                mma16816(s[2*np],   qH[kk], bh0, bh1);
                mma16816(s[2*np+1], qH[kk], bh2, bh3);
                mma16816(s[2*np],   qH[kk], bl0, bl1);
                mma16816(s[2*np+1], qH[kk], bl2, bl3);
                mma16816(s[2*np],   qL[kk], bh0, bh1);
                mma16816(s[2*np+1], qL[kk], bh2, bh3);
            }
        }

        // + bias
#pragma unroll
        for (int j = 0; j < 8; j++) {
            s[j][0] += bb0[j].x; s[j][1] += bb0[j].y;
            s[j][2] += bb1[j].x; s[j][3] += bb1[j].y;
        }

        // online softmax
        float mxA = -INFINITY, mxB = -INFINITY;
#pragma unroll
        for (int j = 0; j < 8; j++) {
            mxA = fmaxf(mxA, fmaxf(s[j][0], s[j][1]));
            mxB = fmaxf(mxB, fmaxf(s[j][2], s[j][3]));
        }
        mxA = fmaxf(mxA, __shfl_xor_sync(0xffffffffu, mxA, 1));
        mxA = fmaxf(mxA, __shfl_xor_sync(0xffffffffu, mxA, 2));
        mxB = fmaxf(mxB, __shfl_xor_sync(0xffffffffu, mxB, 1));
        mxB = fmaxf(mxB, __shfl_xor_sync(0xffffffffu, mxB, 2));

        float mnA = fmaxf(mA, mxA), mnB = fmaxf(mB, mxB);
        float cA = __expf(mA - mnA), cB = __expf(mB - mnB);
        mA = mnA; mB = mnB;

        float sA = 0.f, sB = 0.f;
#pragma unroll
        for (int j = 0; j < 8; j++) {
            s[j][0] = __expf(s[j][0] - mnA);
            s[j][1] = __expf(s[j][1] - mnA);
            s[j][2] = __expf(s[j][2] - mnB);
            s[j][3] = __expf(s[j][3] - mnB);
            sA += s[j][0] + s[j][1];
            sB += s[j][2] + s[j][3];
        }
        sA += __shfl_xor_sync(0xffffffffu, sA, 1);
        sA += __shfl_xor_sync(0xffffffffu, sA, 2);
        sB += __shfl_xor_sync(0xffffffffu, sB, 1);
        sB += __shfl_xor_sync(0xffffffffu, sB, 2);
        lA = lA * cA + sA;
        lB = lB * cB + sB;

#pragma unroll
        for (int j = 0; j < 8; j++) {
            o[j][0] *= cA; o[j][1] *= cA; o[j][2] *= cB; o[j][3] *= cB;
        }

        // O += P V : P split hi/lo in registers, 3-pass (Ph·Vh + Ph·Vl + Pl·Vh)
#pragma unroll
        for (int kk = 0; kk < 4; kk++) {
            uint32_t pH[4], pL[4];
            pack_hilo(s[2*kk][0],   s[2*kk][1],   pH[0], pL[0]);
            pack_hilo(s[2*kk][2],   s[2*kk][3],   pH[1], pL[1]);
            pack_hilo(s[2*kk+1][0], s[2*kk+1][1], pH[2], pL[2]);
            pack_hilo(s[2*kk+1][2], s[2*kk+1][3], pH[3], pL[3]);
#pragma unroll
            for (int np = 0; np < 4; np++) {
                int vrow = kk * 16 + ((lane >> 3) & 1) * 8 + (lane & 7);
                int vcol = np * 16 + (lane >> 4) * 8;
                uint32_t vh0, vh1, vh2, vh3, vl0, vl1, vl2, vl3;
                ldm_x4_t(vh0, vh1, vh2, vh3, smem_u32(&Vh[vrow * AST + vcol]));
                ldm_x4_t(vl0, vl1, vl2, vl3, smem_u32(&Vl[vrow * AST + vcol]));
                mma16816(o[2*np],   pH, vh0, vh1);
                mma16816(o[2*np+1], pH, vh2, vh3);
                mma16816(o[2*np],   pH, vl0, vl1);
                mma16816(o[2*np+1], pH, vl2, vl3);
                mma16816(o[2*np],   pL, vh0, vh1);
                mma16816(o[2*np+1], pL, vh2, vh3);
            }
        }
    }

    // Epilogue: ctx hi/lo in [B, L, E]
    const float invA = 1.f / lA, invB = 1.f / lB;
    const int b = bh >> 4, h = bh & 15;
#pragma unroll
    for (int j = 0; j < 8; j++) {
        int d = j * 8 + colq;
        size_t eA = ((size_t)b * LSEQ + qrowA) * EMB + h * 64 + d;
        size_t eB = eA + (size_t)8 * EMB;
        float v0 = o[j][0] * invA, v1 = o[j][1] * invA;
        float v2 = o[j][2] * invB, v3 = o[j][3] * invB;
        __nv_bfloat16 h0 = __float2bfloat16(v0);
        __nv_bfloat16 h1 = __float2bfloat16(v1);
        __nv_bfloat16 h2 = __float2bfloat16(v2);
        __nv_bfloat16 h3 = __float2bfloat16(v3);
        __nv_bfloat16 l0 = __float2bfloat16(v0 - __bfloat162float(h0));
        __nv_bfloat16 l1 = __float2bfloat16(v1 - __bfloat162float(h1));
        __nv_bfloat16 l2 = __float2bfloat16(v2 - __bfloat162float(h2));
        __nv_bfloat16 l3 = __float2bfloat16(v3 - __bfloat162float(h3));
        *(__nv_bfloat162*)(g_ch + eA) = __nv_bfloat162(h0, h1);
        *(__nv_bfloat162*)(g_cl + eA) = __nv_bfloat162(l0, l1);
        *(__nv_bfloat162*)(g_ch + eB) = __nv_bfloat162(h2, h3);
        *(__nv_bfloat162*)(g_cl + eB) = __nv_bfloat162(l2, l3);
    }
}

// ---------------------------------------------------------------------------
extern "C" void kernel_launch(void* const* d_in, const int* in_sizes, int n_in,
                              void* d_out, int out_size)
{
    const float* X     = (const float*)d_in[0];
    const float* keb   = (const float*)d_in[1];
    const float* w_in  = (const float*)d_in[2];
    const float* b_in  = (const float*)d_in[3];
    const float* w_out = (const float*)d_in[4];
    const float* b_out = (const float*)d_in[5];
    float* out = (float*)d_out;

    cudaFuncSetAttribute(gemm_mma<0>, cudaFuncAttributeMaxDynamicSharedMemorySize, GEMM_SMEM);
    cudaFuncSetAttribute(gemm_mma<1>, cudaFuncAttributeMaxDynamicSharedMemorySize, GEMM_SMEM);
    cudaFuncSetAttribute(attn_mma,    cudaFuncAttributeMaxDynamicSharedMemorySize, ATTN_SMEM);

    // 0) Split inputs into bf16 hi/lo
    cvt_hilo<<<4096, 256>>>(X,     0, M1*EMB/4);
    cvt_hilo<<<3072, 256>>>(w_in,  1, N1*EMB/4);
    cvt_hilo<<<1024, 256>>>(w_out, 2, EMB*EMB/4);

    // 1) QKV projection
    gemm_mma<0><<<dim3(N1/128, M1/128), 256, GEMM_SMEM>>>(b_in, nullptr);

    // 2) Attention with additive ke_bias
    attn_mma<<<dim3(LSEQ/128, BH), 256, ATTN_SMEM>>>(keb);

    // 3) Output projection
    gemm_mma<1><<<dim3(EMB/128, M1/128), 256, GEMM_SMEM>>>(b_out, out);
}

// round 6
// speedup vs baseline: 5.6446x; 1.1028x over previous
#include <cuda_runtime.h>
#include <cuda_bf16.h>
#include <math.h>
#include <stdint.h>

// Problem constants
#define BSZ 2
#define LSEQ 2048
#define EMB 1024
#define NH 16
#define DH 64
#define BH 32          // BSZ*NH
#define M1 4096        // BSZ*LSEQ
#define N1 3072        // 3*EMB

// Scratch (allocation-free)
__device__ __nv_bfloat16 g_xh[M1*EMB],  g_xl[M1*EMB];
__device__ __nv_bfloat16 g_wih[N1*EMB], g_wil[N1*EMB];
__device__ __nv_bfloat16 g_woh[EMB*EMB],g_wol[EMB*EMB];
__device__ __nv_bfloat16 g_qh[BH*LSEQ*DH], g_ql[BH*LSEQ*DH];
__device__ __nv_bfloat16 g_kh[BH*LSEQ*DH], g_kl[BH*LSEQ*DH];
__device__ __nv_bfloat16 g_vh[BH*LSEQ*DH], g_vl[BH*LSEQ*DH];
__device__ __nv_bfloat16 g_ch[M1*EMB],  g_cl[M1*EMB];

// ---------------------------------------------------------------------------
// PTX helpers
// ---------------------------------------------------------------------------
__device__ __forceinline__ uint32_t smem_u32(const void* p) {
    return (uint32_t)__cvta_generic_to_shared(p);
}
__device__ __forceinline__ void ldm_x4(uint32_t& a0, uint32_t& a1,
                                       uint32_t& a2, uint32_t& a3, uint32_t addr) {
    asm volatile("ldmatrix.sync.aligned.m8n8.x4.shared.b16 {%0,%1,%2,%3},[%4];\n"
                 : "=r"(a0), "=r"(a1), "=r"(a2), "=r"(a3) : "r"(addr));
}
__device__ __forceinline__ void ldm_x4_t(uint32_t& a0, uint32_t& a1,
                                         uint32_t& a2, uint32_t& a3, uint32_t addr) {
    asm volatile("ldmatrix.sync.aligned.m8n8.x4.trans.shared.b16 {%0,%1,%2,%3},[%4];\n"
                 : "=r"(a0), "=r"(a1), "=r"(a2), "=r"(a3) : "r"(addr));
}
__device__ __forceinline__ void mma16816(float* c, const uint32_t* a,
                                         uint32_t b0, uint32_t b1) {
    asm volatile("mma.sync.aligned.m16n8k16.row.col.f32.bf16.bf16.f32 "
                 "{%0,%1,%2,%3},{%4,%5,%6,%7},{%8,%9},{%0,%1,%2,%3};\n"
                 : "+f"(c[0]), "+f"(c[1]), "+f"(c[2]), "+f"(c[3])
                 : "r"(a[0]), "r"(a[1]), "r"(a[2]), "r"(a[3]), "r"(b0), "r"(b1));
}
__device__ __forceinline__ void cp16(void* smem_ptr, const void* gptr) {
    asm volatile("cp.async.cg.shared.global [%0], [%1], 16;\n"
                 :: "r"(smem_u32(smem_ptr)), "l"(gptr));
}
__device__ __forceinline__ void cp_commit() {
    asm volatile("cp.async.commit_group;\n");
}
__device__ __forceinline__ void cp_wait0() {
    asm volatile("cp.async.wait_group 0;\n");
}
__device__ __forceinline__ uint32_t packbf(float lo, float hi) {
    uint32_t r;
    asm("cvt.rn.bf16x2.f32 %0, %1, %2;" : "=r"(r) : "f"(hi), "f"(lo));
    return r;
}
__device__ __forceinline__ void pack_hilo(float v0, float v1,
                                          uint32_t& ph, uint32_t& pl) {
    ph = packbf(v0, v1);
    __nv_bfloat162 h = *(__nv_bfloat162*)&ph;
    pl = packbf(v0 - __bfloat162float(h.x), v1 - __bfloat162float(h.y));
}

// ---------------------------------------------------------------------------
// Prep: fp32 -> bf16 hi/lo split
// ---------------------------------------------------------------------------
__global__ __launch_bounds__(256)
void cvt_hilo(const float* __restrict__ src, int sel, int n4)
{
    int i = blockIdx.x * 256 + threadIdx.x;
    if (i >= n4) return;
    __nv_bfloat16 *dh, *dl;
    if (sel == 0)      { dh = g_xh;  dl = g_xl;  }
    else if (sel == 1) { dh = g_wih; dl = g_wil; }
    else               { dh = g_woh; dl = g_wol; }
    float4 v = ((const float4*)src)[i];
    uint32_t h01, l01, h23, l23;
    pack_hilo(v.x, v.y, h01, l01);
    pack_hilo(v.z, v.w, h23, l23);
    ((uint32_t*)dh)[2*i]   = h01;  ((uint32_t*)dh)[2*i+1] = h23;
    ((uint32_t*)dl)[2*i]   = l01;  ((uint32_t*)dl)[2*i+1] = l23;
}

// ---------------------------------------------------------------------------
// GEMM: C[M,N] = A @ W^T + bias. Split-bf16 3-pass mma, cp.async double buffer.
// BM=128, BN=128, BK=32, 256 threads (8 warps: 4m x 2n, warp = 32m x 64n).
// MMA issue order is pass-major round-robin over 4 independent accumulators
// (reuse distance 4) to cover HMMA RAW latency.
// MODE 0: A=g_x*, W=g_wi*; epilogue scatters q(scaled)/k/v hi/lo -> [BH,L,D]
// MODE 1: A=g_c*, W=g_wo*; epilogue writes fp32 C row-major
// ---------------------------------------------------------------------------
#define GST 40
#define GARR 5120           // 128*GST
#define GSTAGE 20480        // 4 arrays per stage
#define GEMM_SMEM (2*GSTAGE*2)  // bytes = 81920

template<int MODE>
__global__ __launch_bounds__(256, 2)
void gemm_mma(const float* __restrict__ bias, float* __restrict__ Cout)
{
    extern __shared__ __nv_bfloat16 smg[];
    const int tid = threadIdx.x, lane = tid & 31, w = tid >> 5;
    const int wm = w >> 1, wn = w & 1;
    const int m0 = blockIdx.y * 128, n0 = blockIdx.x * 128;

    const __nv_bfloat16* Ahg = (MODE == 0) ? g_xh  : g_ch;
    const __nv_bfloat16* Alg = (MODE == 0) ? g_xl  : g_cl;
    const __nv_bfloat16* Whg = (MODE == 0) ? g_wih : g_woh;
    const __nv_bfloat16* Wlg = (MODE == 0) ? g_wil : g_wol;

    const int lr = tid >> 1;            // 0..127
    const int lq = (tid & 1) * 16;      // elem offset 0/16
    const __nv_bfloat16* pAh = Ahg + (size_t)(m0 + lr) * 1024 + lq;
    const __nv_bfloat16* pAl = Alg + (size_t)(m0 + lr) * 1024 + lq;
    const __nv_bfloat16* pWh = Whg + (size_t)(n0 + lr) * 1024 + lq;
    const __nv_bfloat16* pWl = Wlg + (size_t)(n0 + lr) * 1024 + lq;

    auto load_stage = [&](int st, int k0) {
        __nv_bfloat16* b = smg + st * GSTAGE + lr * GST + lq;
        cp16(b,            pAh + k0); cp16(b + 8,          pAh + k0 + 8);
        cp16(b + GARR,     pAl + k0); cp16(b + GARR + 8,   pAl + k0 + 8);
        cp16(b + 2*GARR,   pWh + k0); cp16(b + 2*GARR + 8, pWh + k0 + 8);
        cp16(b + 3*GARR,   pWl + k0); cp16(b + 3*GARR + 8, pWl + k0 + 8);
        cp_commit();
    };

    float c[2][8][4];
#pragma unroll
    for (int a = 0; a < 2; a++)
#pragma unroll
        for (int b = 0; b < 8; b++)
#pragma unroll
            for (int d = 0; d < 4; d++) c[a][b][d] = 0.f;

    load_stage(0, 0);

    for (int it = 0; it < 32; it++) {
        cp_wait0();
        __syncthreads();
        if (it < 31) load_stage((it + 1) & 1, (it + 1) * 32);

        __nv_bfloat16* Ah = smg + (it & 1) * GSTAGE;
        __nv_bfloat16* Al = Ah + GARR;
        __nv_bfloat16* Wh = Ah + 2*GARR;
        __nv_bfloat16* Wl = Ah + 3*GARR;

#pragma unroll
        for (int kk = 0; kk < 2; kk++) {
            uint32_t aH[2][4], aL[2][4];
#pragma unroll
            for (int mt = 0; mt < 2; mt++) {
                int row = wm * 32 + mt * 16 + (lane & 15);
                int kof = kk * 16 + ((lane >> 4) << 3);
                ldm_x4(aH[mt][0], aH[mt][1], aH[mt][2], aH[mt][3],
                       smem_u32(&Ah[row * GST + kof]));
                ldm_x4(aL[mt][0], aL[mt][1], aL[mt][2], aL[mt][3],
                       smem_u32(&Al[row * GST + kof]));
            }
#pragma unroll
            for (int np = 0; np < 4; np++) {
                int row = wn * 64 + np * 16 + ((lane >> 4) << 3) + (lane & 7);
                int kof = kk * 16 + ((lane >> 3) & 1) * 8;
                uint32_t bh0, bh1, bh2, bh3, bl0, bl1, bl2, bl3;
                ldm_x4(bh0, bh1, bh2, bh3, smem_u32(&Wh[row * GST + kof]));
                ldm_x4(bl0, bl1, bl2, bl3, smem_u32(&Wl[row * GST + kof]));
                // pass HH: 4 independent accumulators
                mma16816(c[0][2*np],   aH[0], bh0, bh1);
                mma16816(c[0][2*np+1], aH[0], bh2, bh3);
                mma16816(c[1][2*np],   aH[1], bh0, bh1);
                mma16816(c[1][2*np+1], aH[1], bh2, bh3);
                // pass HL
                mma16816(c[0][2*np],   aH[0], bl0, bl1);
                mma16816(c[0][2*np+1], aH[0], bl2, bl3);
                mma16816(c[1][2*np],   aH[1], bl0, bl1);
                mma16816(c[1][2*np+1], aH[1], bl2, bl3);
                // pass LH
                mma16816(c[0][2*np],   aL[0], bh0, bh1);
                mma16816(c[0][2*np+1], aL[0], bh2, bh3);
                mma16816(c[1][2*np],   aL[1], bh0, bh1);
                mma16816(c[1][2*np+1], aL[1], bh2, bh3);
            }
        }
    }

    // Epilogue
    const int rA = lane >> 2, colq = (lane & 3) * 2;
#pragma unroll
    for (int mt = 0; mt < 2; mt++) {
#pragma unroll
        for (int np = 0; np < 4; np++) {
#pragma unroll
            for (int cc = 0; cc < 2; cc++) {
                int n = n0 + wn * 64 + np * 16 + cc * 8 + colq;
                int mrow = m0 + wm * 32 + mt * 16 + rA;
                float bv0 = bias[n], bv1 = bias[n + 1];
                float* cp = c[mt][2*np + cc];
                float v0 = cp[0] + bv0, v1 = cp[1] + bv1;
                float v2 = cp[2] + bv0, v3 = cp[3] + bv1;
                if (MODE == 0) {
                    int which = n >> 10;
                    int e = n & 1023, hh = e >> 6, d = e & 63;
                    if (which == 0) { v0*=0.125f; v1*=0.125f; v2*=0.125f; v3*=0.125f; }
                    int b = mrow >> 11;
                    size_t dA = (((size_t)(b * NH + hh)) * LSEQ + (mrow & 2047)) * DH + d;
                    size_t dB = dA + 8 * DH;
                    uint32_t h01, l01, h23, l23;
                    pack_hilo(v0, v1, h01, l01);
                    pack_hilo(v2, v3, h23, l23);
                    __nv_bfloat16 *dh, *dl;
                    if (which == 0)      { dh = g_qh; dl = g_ql; }
                    else if (which == 1) { dh = g_kh; dl = g_kl; }
                    else                 { dh = g_vh; dl = g_vl; }
                    *(uint32_t*)(dh + dA) = h01;
                    *(uint32_t*)(dl + dA) = l01;
                    *(uint32_t*)(dh + dB) = h23;
                    *(uint32_t*)(dl + dB) = l23;
                } else {
                    *(float2*)(Cout + (size_t)mrow * EMB + n) = make_float2(v0, v1);
                    *(float2*)(Cout + (size_t)(mrow + 8) * EMB + n) = make_float2(v2, v3);
                }
            }
        }
    }
}

// ---------------------------------------------------------------------------
// Flash attention: QK 3-pass split bf16, PV 3-pass with register hi/lo P,
// K/V double-buffered via cp.async, bias loaded as S accumulator init.
// Grid (L/128, BH), 256 threads, 2 CTAs/SM. Br=128 (16 rows/warp), Bc=64.
// ---------------------------------------------------------------------------
#define AST 72
#define KARR 4608          // 64*AST
#define KSTAGE 18432       // 4 arrays
#define ATTN_SMEM 110592

__global__ __launch_bounds__(256, 2)
void attn_mma(const float* __restrict__ keb)
{
    extern __shared__ __nv_bfloat16 sma[];
    __nv_bfloat16* Qh = sma;
    __nv_bfloat16* Ql = sma + 9216;
    __nv_bfloat16* KVbase = sma + 18432;

    const int tid = threadIdx.x, lane = tid & 31, w = tid >> 5;
    const int bh = blockIdx.y;
    const int q0 = blockIdx.x * 128;
    const size_t hb = (size_t)bh * LSEQ * DH;
    const float* Bg = keb + (size_t)bh * LSEQ * LSEQ;

    const int lr = tid >> 2;           // 0..63
    const int lq = (tid & 3) * 16;     // 0,16,32,48
    const __nv_bfloat16* pKh = g_kh + hb + (size_t)lr * 64 + lq;
    const __nv_bfloat16* pKl = g_kl + hb + (size_t)lr * 64 + lq;
    const __nv_bfloat16* pVh = g_vh + hb + (size_t)lr * 64 + lq;
    const __nv_bfloat16* pVl = g_vl + hb + (size_t)lr * 64 + lq;

    auto load_kv = [&](int st, int k0) {
        __nv_bfloat16* b = KVbase + st * KSTAGE + lr * AST + lq;
        size_t off = (size_t)k0 * 64;
        cp16(b,            pKh + off); cp16(b + 8,          pKh + off + 8);
        cp16(b + KARR,     pKl + off); cp16(b + KARR + 8,   pKl + off + 8);
        cp16(b + 2*KARR,   pVh + off); cp16(b + 2*KARR + 8, pVh + off + 8);
        cp16(b + 3*KARR,   pVl + off); cp16(b + 3*KARR + 8, pVl + off + 8);
        cp_commit();
    };

    load_kv(0, 0);

    // Q tile -> smem
#pragma unroll
    for (int i = 0; i < 4; i++) {
        int id = tid + i * 256;
        int r = id >> 3, c8 = (id & 7) * 8;
        size_t src = hb + (size_t)(q0 + r) * DH + c8;
        *(uint4*)&Qh[r * AST + c8] = *(const uint4*)(g_qh + src);
        *(uint4*)&Ql[r * AST + c8] = *(const uint4*)(g_ql + src);
    }
    __syncthreads();

    uint32_t qH[4][4], qL[4][4];
#pragma unroll
    for (int kk = 0; kk < 4; kk++) {
        int row = w * 16 + (lane & 15);
        int kof = kk * 16 + ((lane >> 4) << 3);
        ldm_x4(qH[kk][0], qH[kk][1], qH[kk][2], qH[kk][3], smem_u32(&Qh[row * AST + kof]));
        ldm_x4(qL[kk][0], qL[kk][1], qL[kk][2], qL[kk][3], smem_u32(&Ql[row * AST + kof]));
    }

    float o[8][4];
#pragma unroll
    for (int j = 0; j < 8; j++)
#pragma unroll
        for (int d = 0; d < 4; d++) o[j][d] = 0.f;
    float mA = -INFINITY, mB = -INFINITY, lA = 0.f, lB = 0.f;

    const int rA = lane >> 2, colq = (lane & 3) * 2;
    const int qrowA = q0 + w * 16 + rA;
    const float* Br0 = Bg + (size_t)qrowA * LSEQ + colq;
    const float* Br1 = Bg + (size_t)(qrowA + 8) * LSEQ + colq;

    for (int it = 0; it < 32; it++) {
        const int k0 = it * 64;

        // S init = bias (LDG latency overlapped with cp wait + kv issue)
        float s[8][4];
#pragma unroll
        for (int j = 0; j < 8; j++) {
            float2 b0 = *(const float2*)(Br0 + k0 + j * 8);
            float2 b1 = *(const float2*)(Br1 + k0 + j * 8);
            s[j][0] = b0.x; s[j][1] = b0.y; s[j][2] = b1.x; s[j][3] = b1.y;
        }

        cp_wait0();
        __syncthreads();
        if (it < 31) load_kv((it + 1) & 1, k0 + 64);

        __nv_bfloat16* Kh = KVbase + (it & 1) * KSTAGE;
        __nv_bfloat16* Kl = Kh + KARR;
        __nv_bfloat16* Vh = Kh + 2*KARR;
        __nv_bfloat16* Vl = Kh + 3*KARR;

        // S += Q K^T (3-pass)
#pragma unroll
        for (int kk = 0; kk < 4; kk++) {
#pragma unroll
            for (int np = 0; np < 4; np++) {
                int row = np * 16 + ((lane >> 4) << 3) + (lane & 7);
                int kof = kk * 16 + ((lane >> 3) & 1) * 8;
                uint32_t bh0, bh1, bh2, bh3, bl0, bl1, bl2, bl3;
                ldm_x4(bh0, bh1, bh2, bh3, smem_u32(&Kh[row * AST + kof]));
                ldm_x4(bl0, bl1, bl2, bl3, smem_u32(&Kl[row * AST + kof]));
                mma16816(s[2*np],   qH[kk], bh0, bh1);
                mma16816(s[2*np+1], qH[kk], bh2, bh3);
                mma16816(s[2*np],   qH[kk], bl0, bl1);
                mma16816(s[2*np+1], qH[kk], bl2, bl3);
                mma16816(s[2*np],   qL[kk], bh0, bh1);
                mma16816(s[2*np+1], qL[kk], bh2, bh3);
            }
        }

        // online softmax
        float mxA = -INFINITY, mxB = -INFINITY;
#pragma unroll
        for (int j = 0; j < 8; j++) {
            mxA = fmaxf(mxA, fmaxf(s[j][0], s[j][1]));
            mxB = fmaxf(mxB, fmaxf(s[j][2], s[j][3]));
        }
        mxA = fmaxf(mxA, __shfl_xor_sync(0xffffffffu, mxA, 1));
        mxA = fmaxf(mxA, __shfl_xor_sync(0xffffffffu, mxA, 2));
        mxB = fmaxf(mxB, __shfl_xor_sync(0xffffffffu, mxB, 1));
        mxB = fmaxf(mxB, __shfl_xor_sync(0xffffffffu, mxB, 2));

        float mnA = fmaxf(mA, mxA), mnB = fmaxf(mB, mxB);
        float cA = __expf(mA - mnA), cB = __expf(mB - mnB);
        mA = mnA; mB = mnB;

        float sA = 0.f, sB = 0.f;
#pragma unroll
        for (int j = 0; j < 8; j++) {
            s[j][0] = __expf(s[j][0] - mnA);
            s[j][1] = __expf(s[j][1] - mnA);
            s[j][2] = __expf(s[j][2] - mnB);
            s[j][3] = __expf(s[j][3] - mnB);
            sA += s[j][0] + s[j][1];
            sB += s[j][2] + s[j][3];
        }
        sA += __shfl_xor_sync(0xffffffffu, sA, 1);
        sA += __shfl_xor_sync(0xffffffffu, sA, 2);
        sB += __shfl_xor_sync(0xffffffffu, sB, 1);
        sB += __shfl_xor_sync(0xffffffffu, sB, 2);
        lA = lA * cA + sA;
        lB = lB * cB + sB;

#pragma unroll
        for (int j = 0; j < 8; j++) {
            o[j][0] *= cA; o[j][1] *= cA; o[j][2] *= cB; o[j][3] *= cB;
        }

        // O += P V : P split hi/lo in registers, 3-pass
#pragma unroll
        for (int kk = 0; kk < 4; kk++) {
            uint32_t pH[4], pL[4];
            pack_hilo(s[2*kk][0],   s[2*kk][1],   pH[0], pL[0]);
            pack_hilo(s[2*kk][2],   s[2*kk][3],   pH[1], pL[1]);
            pack_hilo(s[2*kk+1][0], s[2*kk+1][1], pH[2], pL[2]);
            pack_hilo(s[2*kk+1][2], s[2*kk+1][3], pH[3], pL[3]);
#pragma unroll
            for (int np = 0; np < 4; np++) {
                int vrow = kk * 16 + ((lane >> 3) & 1) * 8 + (lane & 7);
                int vcol = np * 16 + (lane >> 4) * 8;
                uint32_t vh0, vh1, vh2, vh3, vl0, vl1, vl2, vl3;
                ldm_x4_t(vh0, vh1, vh2, vh3, smem_u32(&Vh[vrow * AST + vcol]));
                ldm_x4_t(vl0, vl1, vl2, vl3, smem_u32(&Vl[vrow * AST + vcol]));
                mma16816(o[2*np],   pH, vh0, vh1);
                mma16816(o[2*np+1], pH, vh2, vh3);
                mma16816(o[2*np],   pH, vl0, vl1);
                mma16816(o[2*np+1], pH, vl2, vl3);
                mma16816(o[2*np],   pL, vh0, vh1);
                mma16816(o[2*np+1], pL, vh2, vh3);
            }
        }
    }

    // Epilogue: ctx hi/lo in [B, L, E]
    const float invA = 1.f / lA, invB = 1.f / lB;
    const int b = bh >> 4, h = bh & 15;
#pragma unroll
    for (int j = 0; j < 8; j++) {
        int d = j * 8 + colq;
        size_t eA = ((size_t)b * LSEQ + qrowA) * EMB + h * 64 + d;
        size_t eB = eA + (size_t)8 * EMB;
        uint32_t h01, l01, h23, l23;
        pack_hilo(o[j][0] * invA, o[j][1] * invA, h01, l01);
        pack_hilo(o[j][2] * invB, o[j][3] * invB, h23, l23);
        *(uint32_t*)(g_ch + eA) = h01;
        *(uint32_t*)(g_cl + eA) = l01;
        *(uint32_t*)(g_ch + eB) = h23;
        *(uint32_t*)(g_cl + eB) = l23;
    }
}

// ---------------------------------------------------------------------------
extern "C" void kernel_launch(void* const* d_in, const int* in_sizes, int n_in,
                              void* d_out, int out_size)
{
    const float* X     = (const float*)d_in[0];
    const float* keb   = (const float*)d_in[1];
    const float* w_in  = (const float*)d_in[2];
    const float* b_in  = (const float*)d_in[3];
    const float* w_out = (const float*)d_in[4];
    const float* b_out = (const float*)d_in[5];
    float* out = (float*)d_out;

    cudaFuncSetAttribute(gemm_mma<0>, cudaFuncAttributeMaxDynamicSharedMemorySize, GEMM_SMEM);
    cudaFuncSetAttribute(gemm_mma<1>, cudaFuncAttributeMaxDynamicSharedMemorySize, GEMM_SMEM);
    cudaFuncSetAttribute(attn_mma,    cudaFuncAttributeMaxDynamicSharedMemorySize, ATTN_SMEM);

    // 0) Split inputs into bf16 hi/lo
    cvt_hilo<<<4096, 256>>>(X,     0, M1*EMB/4);
    cvt_hilo<<<3072, 256>>>(w_in,  1, N1*EMB/4);
    cvt_hilo<<<1024, 256>>>(w_out, 2, EMB*EMB/4);

    // 1) QKV projection
    gemm_mma<0><<<dim3(N1/128, M1/128), 256, GEMM_SMEM>>>(b_in, nullptr);

    // 2) Attention with additive ke_bias
    attn_mma<<<dim3(LSEQ/128, BH), 256, ATTN_SMEM>>>(keb);

    // 3) Output projection
    gemm_mma<1><<<dim3(EMB/128, M1/128), 256, GEMM_SMEM>>>(b_out, out);
}